// round 12
// baseline (speedup 1.0000x reference)
#include <cuda_runtime.h>
#include <math.h>

// Problem dims: B=32, T=1024, D=512, H=256 (2H == D)

// ---------------- scratch (device globals; no allocations allowed) ----------------
__device__ float g_xg_f[33554432];   // [B*T, 4H] = 32768 x 1024
__device__ float g_xg_b[33554432];
__device__ float g_xe[16777216];     // [B, T, 512]
__device__ float g_proj[16777216];   // [B, T, 512]
__device__ float g_L[33554432];      // [B, T, T] = 32 x 1024 x 1024
__device__ float g_h[2][2][32][256]; // double-buffered hidden state [buf][dir][b][k]
__device__ unsigned g_bar;
__device__ unsigned g_mask_flags;
__device__ unsigned char g_mask[32768];

__global__ void reset_kernel() { g_bar = 0u; g_mask_flags = 0u; }

// ---- mask dtype detection: bit0 set if any word not in {0,1} (not int32-bool);
//      bit1 set if any word not in {0, 0x3F800000} (not float32-bool).
__global__ void mask_detect_kernel(const unsigned* __restrict__ m) {
    int i = blockIdx.x * 256 + threadIdx.x;  // 8192 words = 32768 bytes, safe for all dtypes
    unsigned v = m[i];
    unsigned f = 0;
    if (v != 0u && v != 1u)           f |= 1u;
    if (v != 0u && v != 0x3F800000u)  f |= 2u;
    if (f) atomicOr(&g_mask_flags, f);
}

__global__ void mask_expand_kernel(const void* __restrict__ m) {
    int i = blockIdx.x * 256 + threadIdx.x;  // 32768
    unsigned flags = g_mask_flags;
    unsigned char r;
    if ((flags & 1u) == 0u)        r = (unsigned char)(((const unsigned*)m)[i] != 0u);      // int32 bool
    else if ((flags & 2u) == 0u)   r = (unsigned char)(((const float*)m)[i] != 0.0f);       // float32 bool
    else                           r = ((const unsigned char*)m)[i] ? 1 : 0;                // uint8 bool
    g_mask[i] = r;
}

__device__ __forceinline__ float sigmoidf_(float x) { return 1.0f / (1.0f + __expf(-x)); }

// ---------------- generic fp32 SGEMM: C = A @ op(B) (+bias), 128x128 tile ----------------
// A row-major [M,K]. TRANSB: B row-major [N,K] (C=A@B^T). !TRANSB: B row-major [K,N].
// All of M,N divisible by 128 and K by 8 for this problem (no bounds checks).
template<bool TRANSB, bool BIAS>
__global__ __launch_bounds__(256) void sgemm_kernel(
    const float* __restrict__ A, const float* __restrict__ B,
    const float* __restrict__ bias, float* __restrict__ C,
    int M, int N, int K, long sA, long sB, long sC)
{
    __shared__ float As[8][128];
    __shared__ float Bs[8][128];

    long bz = blockIdx.z;
    A += bz * sA; B += bz * sB; C += bz * sC;

    int mBase = blockIdx.y * 128;
    int nBase = blockIdx.x * 128;
    int tid  = threadIdx.x;
    int warp = tid >> 5, lane = tid & 31;
    int wr = warp >> 2, wc = warp & 3;   // 2x4 warp grid (64x32 warp tiles)
    int lr = lane >> 2, lc = lane & 3;   // 8x4 lane grid (8x8 thread tiles)
    int row0 = wr * 64 + lr * 8;
    int col0 = wc * 32 + lc * 8;

    float acc[8][8];
#pragma unroll
    for (int i = 0; i < 8; ++i)
#pragma unroll
        for (int j = 0; j < 8; ++j) acc[i][j] = 0.0f;

    // A tile loader: thread -> (row, 4 k's)
    int arow = tid >> 1;
    int akq  = (tid & 1) * 4;
    const float* Aptr = A + (long)(mBase + arow) * K + akq;

    // B tile loader
    const float* Bptr;
    int brow = 0, bkq = 0, bk = 0, bnq = 0;
    if (TRANSB) {
        brow = tid >> 1; bkq = (tid & 1) * 4;
        Bptr = B + (long)(nBase + brow) * K + bkq;
    } else {
        bk = tid >> 5; bnq = lane * 4;
        Bptr = B + (long)bk * N + nBase + bnq;
    }

    for (int k0 = 0; k0 < K; k0 += 8) {
        float4 av = *(const float4*)Aptr; Aptr += 8;
        As[akq + 0][arow] = av.x; As[akq + 1][arow] = av.y;
        As[akq + 2][arow] = av.z; As[akq + 3][arow] = av.w;
        if (TRANSB) {
            float4 bv = *(const float4*)Bptr; Bptr += 8;
            Bs[bkq + 0][brow] = bv.x; Bs[bkq + 1][brow] = bv.y;
            Bs[bkq + 2][brow] = bv.z; Bs[bkq + 3][brow] = bv.w;
        } else {
            float4 bv = *(const float4*)Bptr; Bptr += (long)8 * N;
            *(float4*)&Bs[bk][bnq] = bv;
        }
        __syncthreads();

#pragma unroll
        for (int k = 0; k < 8; ++k) {
            float4 a0 = *(const float4*)&As[k][row0];
            float4 a1 = *(const float4*)&As[k][row0 + 4];
            float4 b0 = *(const float4*)&Bs[k][col0];
            float4 b1 = *(const float4*)&Bs[k][col0 + 4];
            float a[8] = {a0.x, a0.y, a0.z, a0.w, a1.x, a1.y, a1.z, a1.w};
            float b[8] = {b0.x, b0.y, b0.z, b0.w, b1.x, b1.y, b1.z, b1.w};
#pragma unroll
            for (int i = 0; i < 8; ++i)
#pragma unroll
                for (int j = 0; j < 8; ++j) acc[i][j] += a[i] * b[j];
        }
        __syncthreads();
    }

    float bb[8];
#pragma unroll
    for (int j = 0; j < 8; ++j) bb[j] = 0.0f;
    if (BIAS) {
#pragma unroll
        for (int j = 0; j < 8; ++j) bb[j] = bias[nBase + col0 + j];
    }
#pragma unroll
    for (int i = 0; i < 8; ++i) {
        float* cp = C + (long)(mBase + row0 + i) * N + nBase + col0;
        float4 o0 = make_float4(acc[i][0] + bb[0], acc[i][1] + bb[1],
                                acc[i][2] + bb[2], acc[i][3] + bb[3]);
        float4 o1 = make_float4(acc[i][4] + bb[4], acc[i][5] + bb[5],
                                acc[i][6] + bb[6], acc[i][7] + bb[7]);
        *(float4*)cp = o0;
        *(float4*)(cp + 4) = o1;
    }
}

// ---------------- persistent bidirectional LSTM recurrence ----------------
// 128 CTAs: CTA 0..63 forward, 64..127 backward. Each CTA owns 4 hidden units
// (16 gate columns) for all 32 batches. Per step: stage h (global, .cg) -> SMEM,
// compute gate GEMM slice from SMEM, update c (registers) and h, write h to the
// other global buffer + xe, then software grid barrier.
__global__ __launch_bounds__(256) void lstm_rec_kernel(
    const float* __restrict__ xg_f, const float* __restrict__ xg_b,
    const float* __restrict__ Whh_f, const float* __restrict__ Whh_b,
    float* __restrict__ xe)
{
    extern __shared__ float sm[];
    float* W_sh = sm;                 // [256][20] : W_sh[k*20 + gate*4 + u]
    float* h_sh = sm + 256 * 20;      // [32][260] : h_sh[b*260 + k]
    float* gsum = h_sh + 32 * 260;    // [2][32][4][4] : j, b, gate, u

    int tid = threadIdx.x;
    int cta = blockIdx.x;
    int dir = cta >> 6;
    int u0  = (cta & 63) * 4;
    const float* xg  = dir ? xg_b : xg_f;
    const float* Whh = dir ? Whh_b : Whh_f;

    // Load W_hh slice: W_sh[k][gate*4+u] = Whh[gate*256 + u0 + u][k]
    for (int i = tid; i < 16 * 256; i += 256) {
        int col = i >> 8, k = i & 255;
        int g = col >> 2, u = col & 3;
        W_sh[k * 20 + col] = Whh[(long)(g * 256 + u0 + u) * 256 + k];
    }

    int j  = tid >> 7;        // k-half (0: k<128, 1: k>=128)
    int r  = tid & 127;
    int wb = r >> 2;          // batch (dot work)
    int wg = r & 3;           // gate (dot work)
    int cb = tid >> 2, cu = tid & 3;  // cell-update role for tid < 128
    float c_state = 0.0f;

    __syncthreads();

    for (int s = 0; s < 1024; ++s) {
        int t   = dir ? (1023 - s) : s;
        int cur = s & 1;

        // stage h(t-1) into shared (L1 bypass: other CTAs wrote it)
        if (s == 0) {
            for (int i = tid; i < 32 * 260; i += 256) h_sh[i] = 0.0f;
        } else {
            const float* hsrc = &g_h[cur][dir][0][0];
            for (int i = tid * 4; i < 8192; i += 1024) {
                float4 v = __ldcg((const float4*)(hsrc + i));
                int b = i >> 8, k = i & 255;
                *(float4*)(h_sh + b * 260 + k) = v;
            }
        }
        __syncthreads();

        // partial dot: 4 units for (wb, wg) over this thread's k-half
        float a0 = 0.f, a1 = 0.f, a2 = 0.f, a3 = 0.f;
        {
            const float* hrow = h_sh + wb * 260 + j * 128;
            const float* wp   = W_sh + (j * 128) * 20 + wg * 4;
#pragma unroll 8
            for (int k4 = 0; k4 < 128; k4 += 4) {
                float4 hv = *(const float4*)(hrow + k4);
                float4 w0 = *(const float4*)(wp + (k4 + 0) * 20);
                float4 w1 = *(const float4*)(wp + (k4 + 1) * 20);
                float4 w2 = *(const float4*)(wp + (k4 + 2) * 20);
                float4 w3 = *(const float4*)(wp + (k4 + 3) * 20);
                a0 += hv.x * w0.x + hv.y * w1.x + hv.z * w2.x + hv.w * w3.x;
                a1 += hv.x * w0.y + hv.y * w1.y + hv.z * w2.y + hv.w * w3.y;
                a2 += hv.x * w0.z + hv.y * w1.z + hv.z * w2.z + hv.w * w3.z;
                a3 += hv.x * w0.w + hv.y * w1.w + hv.z * w2.w + hv.w * w3.w;
            }
        }
        float* gp = gsum + ((j * 32 + wb) * 4 + wg) * 4;
        gp[0] = a0; gp[1] = a1; gp[2] = a2; gp[3] = a3;
        __syncthreads();

        if (tid < 128) {
            long base = ((long)cb * 1024 + t) * 1024 + u0 + cu;
            float gi = gsum[((cb) * 4 + 0) * 4 + cu] + gsum[((32 + cb) * 4 + 0) * 4 + cu] + xg[base];
            float gf = gsum[((cb) * 4 + 1) * 4 + cu] + gsum[((32 + cb) * 4 + 1) * 4 + cu] + xg[base + 256];
            float gg = gsum[((cb) * 4 + 2) * 4 + cu] + gsum[((32 + cb) * 4 + 2) * 4 + cu] + xg[base + 512];
            float go = gsum[((cb) * 4 + 3) * 4 + cu] + gsum[((32 + cb) * 4 + 3) * 4 + cu] + xg[base + 768];
            c_state = sigmoidf_(gf) * c_state + sigmoidf_(gi) * tanhf(gg);
            float h = sigmoidf_(go) * tanhf(c_state);
            g_h[cur ^ 1][dir][cb][u0 + cu] = h;
            xe[((long)cb * 1024 + t) * 512 + dir * 256 + u0 + cu] = h;
        }

        // ---- software grid barrier (all 128 CTAs co-resident) ----
        __threadfence();
        __syncthreads();
        if (tid == 0) {
            atomicAdd(&g_bar, 1u);
            unsigned target = 128u * (unsigned)(s + 1);
            while (*((volatile unsigned*)&g_bar) < target) { }
            __threadfence();
        }
        __syncthreads();
    }
}

// ---------------- masked softmax over rows of L ----------------
__global__ __launch_bounds__(256) void softmax_kernel(float* __restrict__ L)
{
    int i = blockIdx.x, b = blockIdx.y;
    float* row = L + ((long)b * 1024 + i) * 1024;
    int tid = threadIdx.x;

    if (g_mask[b * 1024 + i]) {
        // reference: whole row set to -1e30 -> softmax is exactly uniform 1/1024
        const float u = 1.0f / 1024.0f;
#pragma unroll
        for (int q = 0; q < 4; ++q) row[tid + q * 256] = u;
        return;
    }

    __shared__ float red[8];
    float v[4];
    float m = -1e30f;
#pragma unroll
    for (int q = 0; q < 4; ++q) { v[q] = row[tid + q * 256]; m = fmaxf(m, v[q]); }
#pragma unroll
    for (int o = 16; o; o >>= 1) m = fmaxf(m, __shfl_xor_sync(0xffffffffu, m, o));
    int warp = tid >> 5, lane = tid & 31;
    if (lane == 0) red[warp] = m;
    __syncthreads();
    if (warp == 0) {
        float x = (lane < 8) ? red[lane] : -1e30f;
#pragma unroll
        for (int o = 4; o; o >>= 1) x = fmaxf(x, __shfl_xor_sync(0xffffffffu, x, o));
        if (lane == 0) red[0] = x;
    }
    __syncthreads();
    m = red[0];

    float sum = 0.0f;
#pragma unroll
    for (int q = 0; q < 4; ++q) { v[q] = __expf(v[q] - m); sum += v[q]; }
#pragma unroll
    for (int o = 16; o; o >>= 1) sum += __shfl_xor_sync(0xffffffffu, sum, o);
    __syncthreads();
    if (lane == 0) red[warp] = sum;
    __syncthreads();
    if (warp == 0) {
        float x = (lane < 8) ? red[lane] : 0.0f;
#pragma unroll
        for (int o = 4; o; o >>= 1) x += __shfl_xor_sync(0xffffffffu, x, o);
        if (lane == 0) red[0] = x;
    }
    __syncthreads();
    float inv = 1.0f / red[0];
#pragma unroll
    for (int q = 0; q < 4; ++q) row[tid + q * 256] = v[q] * inv;
}

// ---------------- launch ----------------
extern "C" void kernel_launch(void* const* d_in, const int* in_sizes, int n_in,
                              void* d_out, int out_size)
{
    const float* x      = (const float*)d_in[0];
    const void*  xmask  = d_in[1];
    const float* W_ih_f = (const float*)d_in[2];
    const float* W_hh_f = (const float*)d_in[3];
    const float* b_f    = (const float*)d_in[4];
    const float* W_ih_b = (const float*)d_in[5];
    const float* W_hh_b = (const float*)d_in[6];
    const float* b_b    = (const float*)d_in[7];
    const float* W_l    = (const float*)d_in[8];
    float* out = (float*)d_out;

    float *xgF, *xgB, *xe, *proj, *L;
    cudaGetSymbolAddress((void**)&xgF,  g_xg_f);
    cudaGetSymbolAddress((void**)&xgB,  g_xg_b);
    cudaGetSymbolAddress((void**)&xe,   g_xe);
    cudaGetSymbolAddress((void**)&proj, g_proj);
    cudaGetSymbolAddress((void**)&L,    g_L);

    // 0) reset flags + canonicalize mask (dtype-agnostic: int32 / float32 / uint8)
    reset_kernel<<<1, 1>>>();
    mask_detect_kernel<<<32, 256>>>((const unsigned*)xmask);
    mask_expand_kernel<<<128, 256>>>(xmask);

    // 1) input projections: xg = x2d @ W_ih^T + b   [32768 x 1024]
    sgemm_kernel<true, true><<<dim3(8, 256, 1), 256>>>(
        x, W_ih_f, b_f, xgF, 32768, 1024, 512, 0, 0, 0);
    sgemm_kernel<true, true><<<dim3(8, 256, 1), 256>>>(
        x, W_ih_b, b_b, xgB, 32768, 1024, 512, 0, 0, 0);

    // 2) bidirectional LSTM recurrence (persistent kernel, grid barrier per step)
    int smem = (256 * 20 + 32 * 260 + 1024) * 4;  // 57,856 B
    cudaFuncSetAttribute(lstm_rec_kernel,
                         cudaFuncAttributeMaxDynamicSharedMemorySize, smem);
    lstm_rec_kernel<<<128, 256, smem>>>(xgF, xgB, W_hh_f, W_hh_b, xe);

    // 3) proj = xe @ W_l^T   [32768 x 512]
    sgemm_kernel<true, false><<<dim3(4, 256, 1), 256>>>(
        xe, W_l, nullptr, proj, 32768, 512, 512, 0, 0, 0);

    // 4) L[b] = proj[b] @ xe[b]^T   batched [1024 x 1024], K=512
    sgemm_kernel<true, false><<<dim3(8, 8, 32), 256>>>(
        proj, xe, nullptr, L, 1024, 1024, 512,
        (long)1024 * 512, (long)1024 * 512, (long)1024 * 1024);

    // 5) masked softmax rows of L
    softmax_kernel<<<dim3(1024, 32), 256>>>(L);

    // 6) out[b] = A[b] @ xe[b]   batched [1024 x 512], K=1024
    sgemm_kernel<false, false><<<dim3(4, 8, 32), 256>>>(
        L, xe, nullptr, out, 1024, 512, 1024,
        (long)1024 * 1024, (long)1024 * 512, (long)1024 * 512);
}

// round 13
// speedup vs baseline: 1.3401x; 1.3401x over previous
#include <cuda_runtime.h>
#include <math.h>

// Problem dims: B=32, T=1024, D=512, H=256 (2H == D)

// ---------------- scratch (device globals; no allocations allowed) ----------------
__device__ float g_xg_f[33554432];   // [B*T, 4H] = 32768 x 1024
__device__ float g_xg_b[33554432];
__device__ float g_xe[16777216];     // [B, T, 512]
__device__ float g_proj[16777216];   // [B, T, 512]
__device__ float g_L[33554432];      // [B, T, T] = 32 x 1024 x 1024
__device__ unsigned g_mask_flags;
__device__ unsigned char g_mask[32768];

__global__ void reset_kernel() { g_mask_flags = 0u; }

// ---- mask dtype detection: bit0 set if any word not in {0,1} (not int32-bool);
//      bit1 set if any word not in {0, 0x3F800000} (not float32-bool).
__global__ void mask_detect_kernel(const unsigned* __restrict__ m) {
    int i = blockIdx.x * 256 + threadIdx.x;  // 8192 words = 32768 bytes, safe for all dtypes
    unsigned v = m[i];
    unsigned f = 0;
    if (v != 0u && v != 1u)           f |= 1u;
    if (v != 0u && v != 0x3F800000u)  f |= 2u;
    if (f) atomicOr(&g_mask_flags, f);
}

__global__ void mask_expand_kernel(const void* __restrict__ m) {
    int i = blockIdx.x * 256 + threadIdx.x;  // 32768
    unsigned flags = g_mask_flags;
    unsigned char r;
    if ((flags & 1u) == 0u)        r = (unsigned char)(((const unsigned*)m)[i] != 0u);      // int32 bool
    else if ((flags & 2u) == 0u)   r = (unsigned char)(((const float*)m)[i] != 0.0f);       // float32 bool
    else                           r = ((const unsigned char*)m)[i] ? 1 : 0;                // uint8 bool
    g_mask[i] = r;
}

__device__ __forceinline__ float sigmoidf_(float x) { return 1.0f / (1.0f + __expf(-x)); }

__device__ __forceinline__ unsigned smem_u32(const void* p) {
    unsigned a;
    asm("{ .reg .u64 t; cvta.to.shared.u64 t, %1; cvt.u32.u64 %0, t; }" : "=r"(a) : "l"(p));
    return a;
}

__device__ __forceinline__ void st_cluster_f32(unsigned local_addr, int rank, float v) {
    unsigned rem;
    asm volatile("mapa.shared::cluster.u32 %0, %1, %2;" : "=r"(rem) : "r"(local_addr), "r"(rank));
    asm volatile("st.shared::cluster.f32 [%0], %1;" :: "r"(rem), "f"(v) : "memory");
}

// ---------------- generic fp32 SGEMM: C = A @ op(B) (+bias), 128x128 tile ----------------
// Double-buffered SMEM tiles + register prefetch: one __syncthreads per k-tile,
// global loads issued one tile ahead (hides L2/DRAM latency behind 512 FMAs/thread).
template<bool TRANSB, bool BIAS>
__global__ __launch_bounds__(256) void sgemm_kernel(
    const float* __restrict__ A, const float* __restrict__ B,
    const float* __restrict__ bias, float* __restrict__ C,
    int M, int N, int K, long sA, long sB, long sC)
{
    __shared__ float As[2][8][128];
    __shared__ float Bs[2][8][128];

    long bz = blockIdx.z;
    A += bz * sA; B += bz * sB; C += bz * sC;

    int mBase = blockIdx.y * 128;
    int nBase = blockIdx.x * 128;
    int tid  = threadIdx.x;
    int warp = tid >> 5, lane = tid & 31;
    int wr = warp >> 2, wc = warp & 3;   // 2x4 warp grid (64x32 warp tiles)
    int lr = lane >> 2, lc = lane & 3;   // 8x4 lane grid (8x8 thread tiles)
    int row0 = wr * 64 + lr * 8;
    int col0 = wc * 32 + lc * 8;

    float acc[8][8];
#pragma unroll
    for (int i = 0; i < 8; ++i)
#pragma unroll
        for (int j = 0; j < 8; ++j) acc[i][j] = 0.0f;

    // A tile loader: thread -> (row, 4 k's)
    int arow = tid >> 1;
    int akq  = (tid & 1) * 4;
    const float* Aptr = A + (long)(mBase + arow) * K + akq;

    // B tile loader
    const float* Bptr;
    int brow = 0, bkq = 0, bk = 0, bnq = 0;
    if (TRANSB) {
        brow = tid >> 1; bkq = (tid & 1) * 4;
        Bptr = B + (long)(nBase + brow) * K + bkq;
    } else {
        bk = tid >> 5; bnq = lane * 4;
        Bptr = B + (long)bk * N + nBase + bnq;
    }

    // prologue: fetch & stage tile 0
    {
        float4 av = *(const float4*)Aptr; Aptr += 8;
        As[0][akq + 0][arow] = av.x; As[0][akq + 1][arow] = av.y;
        As[0][akq + 2][arow] = av.z; As[0][akq + 3][arow] = av.w;
        if (TRANSB) {
            float4 bv = *(const float4*)Bptr; Bptr += 8;
            Bs[0][bkq + 0][brow] = bv.x; Bs[0][bkq + 1][brow] = bv.y;
            Bs[0][bkq + 2][brow] = bv.z; Bs[0][bkq + 3][brow] = bv.w;
        } else {
            float4 bv = *(const float4*)Bptr; Bptr += (long)8 * N;
            *(float4*)&Bs[0][bk][bnq] = bv;
        }
    }
    __syncthreads();

    int p = 0;
    for (int k0 = 0; k0 < K; k0 += 8) {
        bool nx = (k0 + 8) < K;
        float4 av2, bv2;
        if (nx) {
            av2 = *(const float4*)Aptr; Aptr += 8;
            if (TRANSB) { bv2 = *(const float4*)Bptr; Bptr += 8; }
            else        { bv2 = *(const float4*)Bptr; Bptr += (long)8 * N; }
        }

#pragma unroll
        for (int k = 0; k < 8; ++k) {
            float4 a0 = *(const float4*)&As[p][k][row0];
            float4 a1 = *(const float4*)&As[p][k][row0 + 4];
            float4 b0 = *(const float4*)&Bs[p][k][col0];
            float4 b1 = *(const float4*)&Bs[p][k][col0 + 4];
            float a[8] = {a0.x, a0.y, a0.z, a0.w, a1.x, a1.y, a1.z, a1.w};
            float b[8] = {b0.x, b0.y, b0.z, b0.w, b1.x, b1.y, b1.z, b1.w};
#pragma unroll
            for (int i = 0; i < 8; ++i)
#pragma unroll
                for (int j = 0; j < 8; ++j) acc[i][j] += a[i] * b[j];
        }

        if (nx) {
            int q = p ^ 1;
            As[q][akq + 0][arow] = av2.x; As[q][akq + 1][arow] = av2.y;
            As[q][akq + 2][arow] = av2.z; As[q][akq + 3][arow] = av2.w;
            if (TRANSB) {
                Bs[q][bkq + 0][brow] = bv2.x; Bs[q][bkq + 1][brow] = bv2.y;
                Bs[q][bkq + 2][brow] = bv2.z; Bs[q][bkq + 3][brow] = bv2.w;
            } else {
                *(float4*)&Bs[q][bk][bnq] = bv2;
            }
        }
        __syncthreads();
        p ^= 1;
    }

    float bb[8];
#pragma unroll
    for (int j = 0; j < 8; ++j) bb[j] = 0.0f;
    if (BIAS) {
#pragma unroll
        for (int j = 0; j < 8; ++j) bb[j] = bias[nBase + col0 + j];
    }
#pragma unroll
    for (int i = 0; i < 8; ++i) {
        float* cp = C + (long)(mBase + row0 + i) * N + nBase + col0;
        float4 o0 = make_float4(acc[i][0] + bb[0], acc[i][1] + bb[1],
                                acc[i][2] + bb[2], acc[i][3] + bb[3]);
        float4 o1 = make_float4(acc[i][4] + bb[4], acc[i][5] + bb[5],
                                acc[i][6] + bb[6], acc[i][7] + bb[7]);
        *(float4*)cp = o0;
        *(float4*)(cp + 4) = o1;
    }
}

// ---------------- cluster-based bidirectional LSTM recurrence ----------------
// 16 clusters of 8 CTAs. Cluster c: dir = c>>3, batch group bg = c&7 (batches 4bg..4bg+3).
// CTA rank rk owns hidden units [32rk, 32rk+32). W_hh slice (128 rows x 256 k, transposed)
// lives in SMEM; c-state in registers; h exchanged each step via DSMEM stores +
// barrier.cluster (release/acquire) — no global traffic, no grid barrier.
__global__ __launch_bounds__(256, 1) __cluster_dims__(8, 1, 1)
void lstm_cluster_kernel(const float* __restrict__ xg_f, const float* __restrict__ xg_b,
                         const float* __restrict__ Whh_f, const float* __restrict__ Whh_b,
                         float* __restrict__ xe)
{
    extern __shared__ float sm[];
    float* Wt   = sm;                 // [256 k][128 rows]  (row = gate*32 + ul)
    float* hB   = sm + 32768;         // [2 buf][4 b][256 k]
    float* part = sm + 32768 + 2048;  // [8 slice][4 b][128 rows]

    int tid = threadIdx.x;
    int cid = blockIdx.x >> 3;
    int dir = cid >> 3;
    int bg  = cid & 7;
    unsigned rk;
    asm("mov.u32 %0, %%cluster_ctarank;" : "=r"(rk));
    int u0 = (int)rk * 32;

    const float* xg  = dir ? xg_b : xg_f;
    const float* Whh = dir ? Whh_b : Whh_f;

    // Load W slice transposed: Wt[k*128 + r] = Whh[gate*256 + u0 + ul][k], r = gate*32+ul.
    // (lanes cover consecutive r -> conflict-free STS; one-time cost)
    for (int idx = tid; idx < 8192; idx += 256) {
        int r  = idx & 127;
        int k  = (idx >> 7) << 2;
        int gate = r >> 5, ul = r & 31;
        float4 w = *(const float4*)&Whh[(size_t)(gate * 256 + u0 + ul) * 256 + k];
        Wt[(k + 0) * 128 + r] = w.x;
        Wt[(k + 1) * 128 + r] = w.y;
        Wt[(k + 2) * 128 + r] = w.z;
        Wt[(k + 3) * 128 + r] = w.w;
    }
    // h buffer 0 = 0
    for (int i = tid; i < 1024; i += 256) hB[i] = 0.0f;
    __syncthreads();
    asm volatile("barrier.cluster.arrive.aligned;" ::: "memory");
    asm volatile("barrier.cluster.wait.aligned;" ::: "memory");

    int sl = tid >> 5;          // k-slice 0..7 (k in [32*sl, 32*sl+32))
    int rq = tid & 31;          // row quad: rows 4rq..4rq+3
    int r0 = rq * 4;
    int kbase = sl * 32;
    int cb = tid >> 5;          // cell-update batch (tid<128)
    int cu = tid & 31;          // cell-update unit
    int Bglob = bg * 4 + cb;

    unsigned hb_u32 = smem_u32(hB);
    float c_state = 0.0f;
    int cur = 0;

    for (int s = 0; s < 1024; ++s) {
        int t = dir ? (1023 - s) : s;

        // prefetch xg for this step's cell update (hides global latency behind GEMV)
        float xgi = 0.f, xgf = 0.f, xgg = 0.f, xgo = 0.f;
        if (tid < 128) {
            size_t base = ((size_t)Bglob * 1024 + (size_t)t) * 1024 + u0 + cu;
            xgi = __ldg(&xg[base]);
            xgf = __ldg(&xg[base + 256]);
            xgg = __ldg(&xg[base + 512]);
            xgo = __ldg(&xg[base + 768]);
        }

        // partial GEMV: 4 rows x 4 batches over this thread's 32-k slice
        float ac[4][4];
#pragma unroll
        for (int b = 0; b < 4; ++b)
#pragma unroll
            for (int j = 0; j < 4; ++j) ac[b][j] = 0.0f;

        const float* hc = hB + cur * 1024;
        const float* wp = Wt + kbase * 128 + r0;
#pragma unroll
        for (int kk = 0; kk < 32; kk += 4) {
            float4 w0 = *(const float4*)(wp + (kk + 0) * 128);
            float4 w1 = *(const float4*)(wp + (kk + 1) * 128);
            float4 w2 = *(const float4*)(wp + (kk + 2) * 128);
            float4 w3 = *(const float4*)(wp + (kk + 3) * 128);
#pragma unroll
            for (int b = 0; b < 4; ++b) {
                float4 hv = *(const float4*)(hc + b * 256 + kbase + kk);
                ac[b][0] += w0.x * hv.x + w1.x * hv.y + w2.x * hv.z + w3.x * hv.w;
                ac[b][1] += w0.y * hv.x + w1.y * hv.y + w2.y * hv.z + w3.y * hv.w;
                ac[b][2] += w0.z * hv.x + w1.z * hv.y + w2.z * hv.z + w3.z * hv.w;
                ac[b][3] += w0.w * hv.x + w1.w * hv.y + w2.w * hv.z + w3.w * hv.w;
            }
        }
#pragma unroll
        for (int b = 0; b < 4; ++b)
            *(float4*)&part[(sl * 4 + b) * 128 + r0] =
                make_float4(ac[b][0], ac[b][1], ac[b][2], ac[b][3]);
        __syncthreads();

        if (tid < 128) {
            float d0 = 0.f, d1 = 0.f, d2 = 0.f, d3 = 0.f;
#pragma unroll
            for (int s2 = 0; s2 < 8; ++s2) {
                const float* pp = part + (s2 * 4 + cb) * 128 + cu;
                d0 += pp[0];
                d1 += pp[32];
                d2 += pp[64];
                d3 += pp[96];
            }
            float gi = d0 + xgi, gf = d1 + xgf, gG = d2 + xgg, go = d3 + xgo;
            c_state = sigmoidf_(gf) * c_state + sigmoidf_(gi) * tanhf(gG);
            float h = sigmoidf_(go) * tanhf(c_state);

            // broadcast h to all 8 CTAs' next-buffer slot (incl. self) via DSMEM
            unsigned loc = hb_u32 + (unsigned)(((cur ^ 1) * 1024 + cb * 256 + u0 + cu) * 4);
#pragma unroll
            for (int p2 = 0; p2 < 8; ++p2) st_cluster_f32(loc, p2, h);

            xe[((size_t)Bglob * 1024 + (size_t)t) * 512 + dir * 256 + u0 + cu] = h;
        }

        // cluster barrier: release h writes, acquire peers' h (also block-wide sync)
        asm volatile("barrier.cluster.arrive.aligned;" ::: "memory");
        asm volatile("barrier.cluster.wait.aligned;" ::: "memory");
        cur ^= 1;
    }
}

// ---------------- masked softmax over rows of L ----------------
__global__ __launch_bounds__(256) void softmax_kernel(float* __restrict__ L)
{
    int i = blockIdx.x, b = blockIdx.y;
    float* row = L + ((long)b * 1024 + i) * 1024;
    int tid = threadIdx.x;

    if (g_mask[b * 1024 + i]) {
        const float u = 1.0f / 1024.0f;
#pragma unroll
        for (int q = 0; q < 4; ++q) row[tid + q * 256] = u;
        return;
    }

    __shared__ float red[8];
    float v[4];
    float m = -1e30f;
#pragma unroll
    for (int q = 0; q < 4; ++q) { v[q] = row[tid + q * 256]; m = fmaxf(m, v[q]); }
#pragma unroll
    for (int o = 16; o; o >>= 1) m = fmaxf(m, __shfl_xor_sync(0xffffffffu, m, o));
    int warp = tid >> 5, lane = tid & 31;
    if (lane == 0) red[warp] = m;
    __syncthreads();
    if (warp == 0) {
        float x = (lane < 8) ? red[lane] : -1e30f;
#pragma unroll
        for (int o = 4; o; o >>= 1) x = fmaxf(x, __shfl_xor_sync(0xffffffffu, x, o));
        if (lane == 0) red[0] = x;
    }
    __syncthreads();
    m = red[0];

    float sum = 0.0f;
#pragma unroll
    for (int q = 0; q < 4; ++q) { v[q] = __expf(v[q] - m); sum += v[q]; }
#pragma unroll
    for (int o = 16; o; o >>= 1) sum += __shfl_xor_sync(0xffffffffu, sum, o);
    __syncthreads();
    if (lane == 0) red[warp] = sum;
    __syncthreads();
    if (warp == 0) {
        float x = (lane < 8) ? red[lane] : 0.0f;
#pragma unroll
        for (int o = 4; o; o >>= 1) x += __shfl_xor_sync(0xffffffffu, x, o);
        if (lane == 0) red[0] = x;
    }
    __syncthreads();
    float inv = 1.0f / red[0];
#pragma unroll
    for (int q = 0; q < 4; ++q) row[tid + q * 256] = v[q] * inv;
}

// ---------------- launch ----------------
extern "C" void kernel_launch(void* const* d_in, const int* in_sizes, int n_in,
                              void* d_out, int out_size)
{
    const float* x      = (const float*)d_in[0];
    const void*  xmask  = d_in[1];
    const float* W_ih_f = (const float*)d_in[2];
    const float* W_hh_f = (const float*)d_in[3];
    const float* b_f    = (const float*)d_in[4];
    const float* W_ih_b = (const float*)d_in[5];
    const float* W_hh_b = (const float*)d_in[6];
    const float* b_b    = (const float*)d_in[7];
    const float* W_l    = (const float*)d_in[8];
    float* out = (float*)d_out;

    float *xgF, *xgB, *xe, *proj, *L;
    cudaGetSymbolAddress((void**)&xgF,  g_xg_f);
    cudaGetSymbolAddress((void**)&xgB,  g_xg_b);
    cudaGetSymbolAddress((void**)&xe,   g_xe);
    cudaGetSymbolAddress((void**)&proj, g_proj);
    cudaGetSymbolAddress((void**)&L,    g_L);

    // 0) canonicalize mask (dtype-agnostic: int32 / float32 / uint8)
    reset_kernel<<<1, 1>>>();
    mask_detect_kernel<<<32, 256>>>((const unsigned*)xmask);
    mask_expand_kernel<<<128, 256>>>(xmask);

    // 1) input projections: xg = x2d @ W_ih^T + b   [32768 x 1024]
    sgemm_kernel<true, true><<<dim3(8, 256, 1), 256>>>(
        x, W_ih_f, b_f, xgF, 32768, 1024, 512, 0, 0, 0);
    sgemm_kernel<true, true><<<dim3(8, 256, 1), 256>>>(
        x, W_ih_b, b_b, xgB, 32768, 1024, 512, 0, 0, 0);

    // 2) bidirectional LSTM recurrence (16 clusters x 8 CTAs, DSMEM h exchange)
    int smem = (32768 + 2048 + 4096) * 4;  // 155,648 B
    cudaFuncSetAttribute(lstm_cluster_kernel,
                         cudaFuncAttributeMaxDynamicSharedMemorySize, smem);
    lstm_cluster_kernel<<<128, 256, smem>>>(xgF, xgB, W_hh_f, W_hh_b, xe);

    // 3) proj = xe @ W_l^T   [32768 x 512]
    sgemm_kernel<true, false><<<dim3(4, 256, 1), 256>>>(
        xe, W_l, nullptr, proj, 32768, 512, 512, 0, 0, 0);

    // 4) L[b] = proj[b] @ xe[b]^T   batched [1024 x 1024], K=512
    sgemm_kernel<true, false><<<dim3(8, 8, 32), 256>>>(
        proj, xe, nullptr, L, 1024, 1024, 512,
        (long)1024 * 512, (long)1024 * 512, (long)1024 * 1024);

    // 5) masked softmax rows of L
    softmax_kernel<<<dim3(1024, 32), 256>>>(L);

    // 6) out[b] = A[b] @ xe[b]   batched [1024 x 512], K=1024
    sgemm_kernel<false, false><<<dim3(4, 8, 32), 256>>>(
        L, xe, nullptr, out, 1024, 512, 1024,
        (long)1024 * 1024, (long)1024 * 512, (long)1024 * 512);
}

// round 14
// speedup vs baseline: 1.5851x; 1.1828x over previous
#include <cuda_runtime.h>
#include <math.h>

// Problem dims: B=32, T=1024, D=512, H=256 (2H == D)

// ---------------- scratch (device globals; no allocations allowed) ----------------
__device__ float g_xg_f[33554432];   // [B*T, 4H] = 32768 x 1024
__device__ float g_xg_b[33554432];
__device__ float g_xe[16777216];     // [B, T, 512]
__device__ float g_proj[16777216];   // [B, T, 512]
__device__ float g_L[33554432];      // [B, T, T] = 32 x 1024 x 1024
__device__ unsigned g_mask_flags;
__device__ unsigned char g_mask[32768];

__global__ void reset_kernel() { g_mask_flags = 0u; }

// ---- mask dtype detection (int32 / float32 / uint8 bool) ----
__global__ void mask_detect_kernel(const unsigned* __restrict__ m) {
    int i = blockIdx.x * 256 + threadIdx.x;  // 8192 words = 32768 bytes, safe for all dtypes
    unsigned v = m[i];
    unsigned f = 0;
    if (v != 0u && v != 1u)           f |= 1u;
    if (v != 0u && v != 0x3F800000u)  f |= 2u;
    if (f) atomicOr(&g_mask_flags, f);
}

__global__ void mask_expand_kernel(const void* __restrict__ m) {
    int i = blockIdx.x * 256 + threadIdx.x;  // 32768
    unsigned flags = g_mask_flags;
    unsigned char r;
    if ((flags & 1u) == 0u)        r = (unsigned char)(((const unsigned*)m)[i] != 0u);
    else if ((flags & 2u) == 0u)   r = (unsigned char)(((const float*)m)[i] != 0.0f);
    else                           r = ((const unsigned char*)m)[i] ? 1 : 0;
    g_mask[i] = r;
}

__device__ __forceinline__ float sigmoidf_(float x) { return 1.0f / (1.0f + __expf(-x)); }

__device__ __forceinline__ unsigned smem_u32(const void* p) {
    unsigned a;
    asm("{ .reg .u64 t; cvta.to.shared.u64 t, %1; cvt.u32.u64 %0, t; }" : "=r"(a) : "l"(p));
    return a;
}

__device__ __forceinline__ void st_cluster_f32(unsigned local_addr, int rank, float v) {
    unsigned rem;
    asm volatile("mapa.shared::cluster.u32 %0, %1, %2;" : "=r"(rem) : "r"(local_addr), "r"(rank));
    asm volatile("st.shared::cluster.f32 [%0], %1;" :: "r"(rem), "f"(v) : "memory");
}

// ---- packed f32x2 helpers (FFMA2: 2 fp32 MACs per fma-pipe slot, exact fp32 rounding) ----
__device__ __forceinline__ unsigned long long pack2(float lo, float hi) {
    unsigned long long r;
    asm("mov.b64 %0, {%1, %2};" : "=l"(r) : "f"(lo), "f"(hi));
    return r;
}
__device__ __forceinline__ void fma2(unsigned long long& d, unsigned long long a,
                                     unsigned long long b) {
    asm("fma.rn.f32x2 %0, %1, %2, %0;" : "+l"(d) : "l"(a), "l"(b));
}
__device__ __forceinline__ float2 unpack2(unsigned long long v) {
    float2 r;
    asm("mov.b64 {%0, %1}, %2;" : "=f"(r.x), "=f"(r.y) : "l"(v));
    return r;
}

// ---------------- generic fp32 SGEMM: C = A @ op(B) (+bias), 128x128 tile ----------------
// Double-buffered SMEM + register prefetch; inner product via f32x2 FFMA2
// (32 FFMA2 + 8 ALU packs per k instead of 64 FFMA).
template<bool TRANSB, bool BIAS>
__global__ __launch_bounds__(256) void sgemm_kernel(
    const float* __restrict__ A, const float* __restrict__ B,
    const float* __restrict__ bias, float* __restrict__ C,
    int M, int N, int K, long sA, long sB, long sC)
{
    __shared__ float As[2][8][128];
    __shared__ float Bs[2][8][128];

    long bz = blockIdx.z;
    A += bz * sA; B += bz * sB; C += bz * sC;

    int mBase = blockIdx.y * 128;
    int nBase = blockIdx.x * 128;
    int tid  = threadIdx.x;
    int warp = tid >> 5, lane = tid & 31;
    int wr = warp >> 2, wc = warp & 3;   // 2x4 warp grid (64x32 warp tiles)
    int lr = lane >> 2, lc = lane & 3;   // 8x4 lane grid (8x8 thread tiles)
    int row0 = wr * 64 + lr * 8;
    int col0 = wc * 32 + lc * 8;

    unsigned long long acc2[8][4];
#pragma unroll
    for (int i = 0; i < 8; ++i)
#pragma unroll
        for (int j = 0; j < 4; ++j) acc2[i][j] = 0ull;

    int arow = tid >> 1;
    int akq  = (tid & 1) * 4;
    const float* Aptr = A + (long)(mBase + arow) * K + akq;

    const float* Bptr;
    int brow = 0, bkq = 0, bk = 0, bnq = 0;
    if (TRANSB) {
        brow = tid >> 1; bkq = (tid & 1) * 4;
        Bptr = B + (long)(nBase + brow) * K + bkq;
    } else {
        bk = tid >> 5; bnq = lane * 4;
        Bptr = B + (long)bk * N + nBase + bnq;
    }

    // prologue: fetch & stage tile 0
    {
        float4 av = *(const float4*)Aptr; Aptr += 8;
        As[0][akq + 0][arow] = av.x; As[0][akq + 1][arow] = av.y;
        As[0][akq + 2][arow] = av.z; As[0][akq + 3][arow] = av.w;
        if (TRANSB) {
            float4 bv = *(const float4*)Bptr; Bptr += 8;
            Bs[0][bkq + 0][brow] = bv.x; Bs[0][bkq + 1][brow] = bv.y;
            Bs[0][bkq + 2][brow] = bv.z; Bs[0][bkq + 3][brow] = bv.w;
        } else {
            float4 bv = *(const float4*)Bptr; Bptr += (long)8 * N;
            *(float4*)&Bs[0][bk][bnq] = bv;
        }
    }
    __syncthreads();

    int p = 0;
    for (int k0 = 0; k0 < K; k0 += 8) {
        bool nx = (k0 + 8) < K;
        float4 av2, bv2;
        if (nx) {
            av2 = *(const float4*)Aptr; Aptr += 8;
            if (TRANSB) { bv2 = *(const float4*)Bptr; Bptr += 8; }
            else        { bv2 = *(const float4*)Bptr; Bptr += (long)8 * N; }
        }

#pragma unroll
        for (int k = 0; k < 8; ++k) {
            float4 a0 = *(const float4*)&As[p][k][row0];
            float4 a1 = *(const float4*)&As[p][k][row0 + 4];
            ulonglong2 bq0 = *(const ulonglong2*)&Bs[p][k][col0];
            ulonglong2 bq1 = *(const ulonglong2*)&Bs[p][k][col0 + 4];
            unsigned long long b2[4] = {bq0.x, bq0.y, bq1.x, bq1.y};
            float a[8] = {a0.x, a0.y, a0.z, a0.w, a1.x, a1.y, a1.z, a1.w};
#pragma unroll
            for (int i = 0; i < 8; ++i) {
                unsigned long long ai = pack2(a[i], a[i]);
                fma2(acc2[i][0], ai, b2[0]);
                fma2(acc2[i][1], ai, b2[1]);
                fma2(acc2[i][2], ai, b2[2]);
                fma2(acc2[i][3], ai, b2[3]);
            }
        }

        if (nx) {
            int q = p ^ 1;
            As[q][akq + 0][arow] = av2.x; As[q][akq + 1][arow] = av2.y;
            As[q][akq + 2][arow] = av2.z; As[q][akq + 3][arow] = av2.w;
            if (TRANSB) {
                Bs[q][bkq + 0][brow] = bv2.x; Bs[q][bkq + 1][brow] = bv2.y;
                Bs[q][bkq + 2][brow] = bv2.z; Bs[q][bkq + 3][brow] = bv2.w;
            } else {
                *(float4*)&Bs[q][bk][bnq] = bv2;
            }
        }
        __syncthreads();
        p ^= 1;
    }

    float bb[8];
#pragma unroll
    for (int j = 0; j < 8; ++j) bb[j] = 0.0f;
    if (BIAS) {
#pragma unroll
        for (int j = 0; j < 8; ++j) bb[j] = bias[nBase + col0 + j];
    }
#pragma unroll
    for (int i = 0; i < 8; ++i) {
        float2 q0 = unpack2(acc2[i][0]);
        float2 q1 = unpack2(acc2[i][1]);
        float2 q2 = unpack2(acc2[i][2]);
        float2 q3 = unpack2(acc2[i][3]);
        float* cp = C + (long)(mBase + row0 + i) * N + nBase + col0;
        float4 o0 = make_float4(q0.x + bb[0], q0.y + bb[1], q1.x + bb[2], q1.y + bb[3]);
        float4 o1 = make_float4(q2.x + bb[4], q2.y + bb[5], q3.x + bb[6], q3.y + bb[7]);
        *(float4*)cp = o0;
        *(float4*)(cp + 4) = o1;
    }
}

// ---------------- cluster-based bidirectional LSTM recurrence ----------------
// 16 clusters of 8 CTAs. Cluster c: dir = c>>3, batches 4(c&7)..+3. CTA rank rk owns
// hidden units [32rk, 32rk+32). W_hh slice lives in REGISTERS (128 floats/thread,
// packed f32x2 row-pairs); h exchanged each step via DSMEM stores + barrier.cluster.
// Per-step fma-pipe floor: 256 FFMA2/thread.
__global__ __launch_bounds__(256, 1) __cluster_dims__(8, 1, 1)
void lstm_cluster_kernel(const float* __restrict__ xg_f, const float* __restrict__ xg_b,
                         const float* __restrict__ Whh_f, const float* __restrict__ Whh_b,
                         float* __restrict__ xe)
{
    extern __shared__ float sm[];
    float* hB   = sm;            // [2 buf][4 b][256 k]
    float* part = sm + 2048;     // [8 slice][4 b][128 rows]

    int tid = threadIdx.x;
    int cid = blockIdx.x >> 3;
    int dir = cid >> 3;
    int bg  = cid & 7;
    unsigned rk;
    asm("mov.u32 %0, %%cluster_ctarank;" : "=r"(rk));
    int u0 = (int)rk * 32;

    const float* xg  = dir ? xg_b : xg_f;
    const float* Whh = dir ? Whh_b : Whh_f;

    int sl = tid >> 5;          // k-slice 0..7 (k in [32*sl, 32*sl+32))
    int rq = tid & 31;          // row quad: rows 4rq..4rq+3 (row = gate*32 + unit_local)
    int r0 = rq * 4;
    int kbase = sl * 32;
    int cb = tid >> 5;          // cell-update batch (tid<128)
    int cu = tid & 31;          // cell-update unit
    int Bglob = bg * 4 + cb;

    // ---- load W slice into registers, packed as f32x2 row-pairs ----
    // rows r0..r0+3 share the same gate (r0 is 4-aligned, gate boundary = 32)
    unsigned long long w2[32][2];
    {
        int gate = r0 >> 5, ul0 = r0 & 31;
        const float* p0 = Whh + (size_t)(gate * 256 + u0 + ul0) * 256 + kbase;
#pragma unroll
        for (int q = 0; q < 8; ++q) {
            float4 wa = *(const float4*)(p0 + 0 * 256 + q * 4);
            float4 wb = *(const float4*)(p0 + 1 * 256 + q * 4);
            float4 wc = *(const float4*)(p0 + 2 * 256 + q * 4);
            float4 wd = *(const float4*)(p0 + 3 * 256 + q * 4);
            w2[q * 4 + 0][0] = pack2(wa.x, wb.x); w2[q * 4 + 0][1] = pack2(wc.x, wd.x);
            w2[q * 4 + 1][0] = pack2(wa.y, wb.y); w2[q * 4 + 1][1] = pack2(wc.y, wd.y);
            w2[q * 4 + 2][0] = pack2(wa.z, wb.z); w2[q * 4 + 2][1] = pack2(wc.z, wd.z);
            w2[q * 4 + 3][0] = pack2(wa.w, wb.w); w2[q * 4 + 3][1] = pack2(wc.w, wd.w);
        }
    }

    // h buffer 0 = 0
    for (int i = tid; i < 2048; i += 256) hB[i] = 0.0f;
    __syncthreads();
    asm volatile("barrier.cluster.arrive.aligned;" ::: "memory");
    asm volatile("barrier.cluster.wait.aligned;" ::: "memory");

    unsigned hb_u32 = smem_u32(hB);
    float c_state = 0.0f;
    int cur = 0;

    for (int s = 0; s < 1024; ++s) {
        int t = dir ? (1023 - s) : s;

        // prefetch xg for this step's cell update
        float xgi = 0.f, xgf = 0.f, xgg = 0.f, xgo = 0.f;
        if (tid < 128) {
            size_t base = ((size_t)Bglob * 1024 + (size_t)t) * 1024 + u0 + cu;
            xgi = __ldg(&xg[base]);
            xgf = __ldg(&xg[base + 256]);
            xgg = __ldg(&xg[base + 512]);
            xgo = __ldg(&xg[base + 768]);
        }

        // partial GEMV: 4 row-pairs x 4 batches over this thread's 32-k slice.
        // h reads are warp-broadcast LDS (all lanes same address).
        unsigned long long ac2[4][2];
#pragma unroll
        for (int b = 0; b < 4; ++b) { ac2[b][0] = 0ull; ac2[b][1] = 0ull; }

        const float* hc = hB + cur * 1024 + kbase;
#pragma unroll
        for (int q = 0; q < 8; ++q) {
            float hv[4][4];
#pragma unroll
            for (int b = 0; b < 4; ++b)
                *(float4*)hv[b] = *(const float4*)(hc + b * 256 + q * 4);
#pragma unroll
            for (int e = 0; e < 4; ++e) {
                int kk = q * 4 + e;
#pragma unroll
                for (int b = 0; b < 4; ++b) {
                    unsigned long long h2 = pack2(hv[b][e], hv[b][e]);
                    fma2(ac2[b][0], h2, w2[kk][0]);
                    fma2(ac2[b][1], h2, w2[kk][1]);
                }
            }
        }
#pragma unroll
        for (int b = 0; b < 4; ++b) {
            float2 lo = unpack2(ac2[b][0]);
            float2 hi = unpack2(ac2[b][1]);
            *(float4*)&part[(sl * 4 + b) * 128 + r0] =
                make_float4(lo.x, lo.y, hi.x, hi.y);
        }
        __syncthreads();

        if (tid < 128) {
            float d0 = 0.f, d1 = 0.f, d2 = 0.f, d3 = 0.f;
#pragma unroll
            for (int s2 = 0; s2 < 8; ++s2) {
                const float* pp = part + (s2 * 4 + cb) * 128 + cu;
                d0 += pp[0];
                d1 += pp[32];
                d2 += pp[64];
                d3 += pp[96];
            }
            float gi = d0 + xgi, gf = d1 + xgf, gG = d2 + xgg, go = d3 + xgo;
            c_state = sigmoidf_(gf) * c_state + sigmoidf_(gi) * tanhf(gG);
            float h = sigmoidf_(go) * tanhf(c_state);

            // broadcast h to all 8 CTAs' next-buffer slot (incl. self) via DSMEM
            unsigned loc = hb_u32 + (unsigned)(((cur ^ 1) * 1024 + cb * 256 + u0 + cu) * 4);
#pragma unroll
            for (int p2 = 0; p2 < 8; ++p2) st_cluster_f32(loc, p2, h);

            xe[((size_t)Bglob * 1024 + (size_t)t) * 512 + dir * 256 + u0 + cu] = h;
        }

        // cluster barrier: release h writes, acquire peers' h (also block-wide sync)
        asm volatile("barrier.cluster.arrive.aligned;" ::: "memory");
        asm volatile("barrier.cluster.wait.aligned;" ::: "memory");
        cur ^= 1;
    }
}

// ---------------- masked softmax over rows of L ----------------
__global__ __launch_bounds__(256) void softmax_kernel(float* __restrict__ L)
{
    int i = blockIdx.x, b = blockIdx.y;
    float* row = L + ((long)b * 1024 + i) * 1024;
    int tid = threadIdx.x;

    if (g_mask[b * 1024 + i]) {
        const float u = 1.0f / 1024.0f;
#pragma unroll
        for (int q = 0; q < 4; ++q) row[tid + q * 256] = u;
        return;
    }

    __shared__ float red[8];
    float v[4];
    float m = -1e30f;
#pragma unroll
    for (int q = 0; q < 4; ++q) { v[q] = row[tid + q * 256]; m = fmaxf(m, v[q]); }
#pragma unroll
    for (int o = 16; o; o >>= 1) m = fmaxf(m, __shfl_xor_sync(0xffffffffu, m, o));
    int warp = tid >> 5, lane = tid & 31;
    if (lane == 0) red[warp] = m;
    __syncthreads();
    if (warp == 0) {
        float x = (lane < 8) ? red[lane] : -1e30f;
#pragma unroll
        for (int o = 4; o; o >>= 1) x = fmaxf(x, __shfl_xor_sync(0xffffffffu, x, o));
        if (lane == 0) red[0] = x;
    }
    __syncthreads();
    m = red[0];

    float sum = 0.0f;
#pragma unroll
    for (int q = 0; q < 4; ++q) { v[q] = __expf(v[q] - m); sum += v[q]; }
#pragma unroll
    for (int o = 16; o; o >>= 1) sum += __shfl_xor_sync(0xffffffffu, sum, o);
    __syncthreads();
    if (lane == 0) red[warp] = sum;
    __syncthreads();
    if (warp == 0) {
        float x = (lane < 8) ? red[lane] : 0.0f;
#pragma unroll
        for (int o = 4; o; o >>= 1) x += __shfl_xor_sync(0xffffffffu, x, o);
        if (lane == 0) red[0] = x;
    }
    __syncthreads();
    float inv = 1.0f / red[0];
#pragma unroll
    for (int q = 0; q < 4; ++q) row[tid + q * 256] = v[q] * inv;
}

// ---------------- launch ----------------
extern "C" void kernel_launch(void* const* d_in, const int* in_sizes, int n_in,
                              void* d_out, int out_size)
{
    const float* x      = (const float*)d_in[0];
    const void*  xmask  = d_in[1];
    const float* W_ih_f = (const float*)d_in[2];
    const float* W_hh_f = (const float*)d_in[3];
    const float* b_f    = (const float*)d_in[4];
    const float* W_ih_b = (const float*)d_in[5];
    const float* W_hh_b = (const float*)d_in[6];
    const float* b_b    = (const float*)d_in[7];
    const float* W_l    = (const float*)d_in[8];
    float* out = (float*)d_out;

    float *xgF, *xgB, *xe, *proj, *L;
    cudaGetSymbolAddress((void**)&xgF,  g_xg_f);
    cudaGetSymbolAddress((void**)&xgB,  g_xg_b);
    cudaGetSymbolAddress((void**)&xe,   g_xe);
    cudaGetSymbolAddress((void**)&proj, g_proj);
    cudaGetSymbolAddress((void**)&L,    g_L);

    // 0) canonicalize mask (dtype-agnostic: int32 / float32 / uint8)
    reset_kernel<<<1, 1>>>();
    mask_detect_kernel<<<32, 256>>>((const unsigned*)xmask);
    mask_expand_kernel<<<128, 256>>>(xmask);

    // 1) input projections: xg = x2d @ W_ih^T + b   [32768 x 1024]
    sgemm_kernel<true, true><<<dim3(8, 256, 1), 256>>>(
        x, W_ih_f, b_f, xgF, 32768, 1024, 512, 0, 0, 0);
    sgemm_kernel<true, true><<<dim3(8, 256, 1), 256>>>(
        x, W_ih_b, b_b, xgB, 32768, 1024, 512, 0, 0, 0);

    // 2) bidirectional LSTM recurrence (16 clusters x 8 CTAs, W in registers, DSMEM h)
    int smem = (2048 + 4096) * 4;  // 24,576 B
    cudaFuncSetAttribute(lstm_cluster_kernel,
                         cudaFuncAttributeMaxDynamicSharedMemorySize, smem);
    lstm_cluster_kernel<<<128, 256, smem>>>(xgF, xgB, W_hh_f, W_hh_b, xe);

    // 3) proj = xe @ W_l^T   [32768 x 512]
    sgemm_kernel<true, false><<<dim3(4, 256, 1), 256>>>(
        xe, W_l, nullptr, proj, 32768, 512, 512, 0, 0, 0);

    // 4) L[b] = proj[b] @ xe[b]^T   batched [1024 x 1024], K=512
    sgemm_kernel<true, false><<<dim3(8, 8, 32), 256>>>(
        proj, xe, nullptr, L, 1024, 1024, 512,
        (long)1024 * 512, (long)1024 * 512, (long)1024 * 1024);

    // 5) masked softmax rows of L
    softmax_kernel<<<dim3(1024, 32), 256>>>(L);

    // 6) out[b] = A[b] @ xe[b]   batched [1024 x 512], K=1024
    sgemm_kernel<false, false><<<dim3(4, 8, 32), 256>>>(
        L, xe, nullptr, out, 1024, 512, 1024,
        (long)1024 * 1024, (long)1024 * 512, (long)1024 * 512);
}